// round 4
// baseline (speedup 1.0000x reference)
#include <cuda_runtime.h>
#include <cstdint>

// Problem constants (fixed by the reference):
//   BATCH*SEQ = 65536 tokens, HIDDEN = 768, 8 hashes x 16384 buckets x 96-float shards.
#define NUM_HASHES   8
#define NUM_BUCKETS  16384
#define SHARD        96
#define HIDDEN       768
#define LN_EPS       1e-6f

__constant__ int c_primes[NUM_HASHES] = {31, 43, 59, 61, 73, 97, 103, 113};

// Set by detect_dtype_kernel on every launch sequence: 1 if ids buffer truly
// holds int64 values, 0 if it holds int32 (JAX x64-disabled downgrades
// jnp.int64 randint to int32 silently).
__device__ int g_ids_are_64;

// One block, 512 threads. Reads the first 512 aligned 64-bit words of the ids
// buffer (in-bounds for both dtype interpretations at n_tokens=65536; 4KB is
// also < the smallest plausible ids buffer of 256KB). Genuine int64 ids are
// < 2^32, so any word with high bits set proves the data is packed int32.
__global__ void detect_dtype_kernel(const unsigned long long* __restrict__ ids_as_u64)
{
    __shared__ int any_high;
    if (threadIdx.x == 0) any_high = 0;
    __syncthreads();
    if (ids_as_u64[threadIdx.x] > 0xFFFFFFFFull) atomicOr(&any_high, 1);
    __syncthreads();
    if (threadIdx.x == 0) g_ids_are_64 = (any_high == 0) ? 1 : 0;
}

// One warp per token. Each lane owns 6 float4s (24 floats) of the 768-wide row.
__global__ __launch_bounds__(256) void canine_emb_ln_kernel(
    const void*      __restrict__ ids_raw, // [n_tokens] int32 OR int64
    const float*     __restrict__ tables,  // [8, 16384, 96] f32
    const float*     __restrict__ ln_scale,// [768]
    const float*     __restrict__ ln_bias, // [768]
    float*           __restrict__ out,     // [n_tokens, 768]
    int n_tokens)
{
    const int warp = (blockIdx.x * blockDim.x + threadIdx.x) >> 5;
    const int lane = threadIdx.x & 31;
    if (warp >= n_tokens) return;

    // ids are in [0, 1114112): (id+1)*prime fits in int32, result non-negative.
    int id;
    if (g_ids_are_64) id = (int)((const long long*)ids_raw)[warp];
    else              id = ((const int*)ids_raw)[warp];
    const int idp = id + 1;

    int bucket[NUM_HASHES];
#pragma unroll
    for (int h = 0; h < NUM_HASHES; h++)
        bucket[h] = (idp * c_primes[h]) & (NUM_BUCKETS - 1);

    // Gather 6 float4s per lane. float4 index j = lane + 32*k in [0,192).
    // Shard h = j / 24 (each shard is 24 float4s = 96 floats), matching the
    // reference's hidden layout: hash h occupies columns [96h, 96h+96).
    float4 v[6];
#pragma unroll
    for (int k = 0; k < 6; k++) {
        const int j   = lane + 32 * k;
        const int h   = j / 24;
        const int off = j - 24 * h;
        const float4* row = reinterpret_cast<const float4*>(
            tables + ((size_t)h * NUM_BUCKETS + bucket[h]) * SHARD);
        v[k] = __ldg(row + off);
    }

    // Warp reduction: sum and sum-of-squares over 768 values.
    float s = 0.f, ss = 0.f;
#pragma unroll
    for (int k = 0; k < 6; k++) {
        s  += v[k].x + v[k].y + v[k].z + v[k].w;
        ss += v[k].x * v[k].x + v[k].y * v[k].y
            + v[k].z * v[k].z + v[k].w * v[k].w;
    }
#pragma unroll
    for (int d = 16; d > 0; d >>= 1) {
        s  += __shfl_xor_sync(0xFFFFFFFFu, s,  d);
        ss += __shfl_xor_sync(0xFFFFFFFFu, ss, d);
    }

    const float inv_n = 1.0f / (float)HIDDEN;
    const float mean  = s * inv_n;
    const float var   = fmaxf(ss * inv_n - mean * mean, 0.0f);
    const float rstd  = rsqrtf(var + LN_EPS);

    // Normalize + affine, coalesced float4 stores (512B per warp per k).
    const float4* sc4 = reinterpret_cast<const float4*>(ln_scale);
    const float4* bi4 = reinterpret_cast<const float4*>(ln_bias);
    float4* o4 = reinterpret_cast<float4*>(out + (size_t)warp * HIDDEN);

#pragma unroll
    for (int k = 0; k < 6; k++) {
        const int j = lane + 32 * k;
        const float4 sc = __ldg(sc4 + j);
        const float4 bi = __ldg(bi4 + j);
        float4 r;
        r.x = (v[k].x - mean) * rstd * sc.x + bi.x;
        r.y = (v[k].y - mean) * rstd * sc.y + bi.y;
        r.z = (v[k].z - mean) * rstd * sc.z + bi.z;
        r.w = (v[k].w - mean) * rstd * sc.w + bi.w;
        o4[j] = r;
    }
}

extern "C" void kernel_launch(void* const* d_in, const int* in_sizes, int n_in,
                              void* d_out, int out_size)
{
    const void*  ids    = d_in[0];                 // int32 or int64 input_ids
    const float* tables = (const float*)d_in[1];   // [8,16384,96]
    const float* scale  = (const float*)d_in[2];   // [768]
    const float* bias   = (const float*)d_in[3];   // [768]
    float*       out    = (float*)d_out;

    const int n_tokens = in_sizes[0];              // BATCH*SEQ = 65536

    detect_dtype_kernel<<<1, 512>>>((const unsigned long long*)ids);

    const int warps_per_block = 256 / 32;          // 8 warps/block
    const int blocks = (n_tokens + warps_per_block - 1) / warps_per_block;
    canine_emb_ln_kernel<<<blocks, 256>>>(ids, tables, scale, bias, out, n_tokens);
}

// round 6
// speedup vs baseline: 1.1511x; 1.1511x over previous
#include <cuda_runtime.h>
#include <cstdint>

// Problem constants (fixed by the reference):
//   BATCH*SEQ = 65536 tokens, HIDDEN = 768, 8 hashes x 16384 buckets x 96-float shards.
#define NUM_HASHES   8
#define NUM_BUCKETS  16384
#define SHARD        96
#define HIDDEN       768
#define LN_EPS       1e-6f

// Primes {31,43,59,61,73,97,103,113} packed as little-endian bytes.
#define PACKED_PRIMES 0x716761493D3B2B1Full

// One warp per token. Each lane owns 6 float4s (24 floats) of the 768-wide row.
// Dtype of ids (int32 vs int64) is detected per-warp from the buffer prefix:
// JAX with x64 disabled silently downgrades jnp.int64 randint to int32.
__global__ __launch_bounds__(256) void canine_emb_ln_kernel(
    const void*      __restrict__ ids_raw, // [n_tokens] int32 OR int64
    const float*     __restrict__ tables,  // [8, 16384, 96] f32
    const float*     __restrict__ ln_scale,// [768]
    const float*     __restrict__ ln_bias, // [768]
    float*           __restrict__ out,     // [n_tokens, 768]
    int n_tokens)
{
    const int warp = (blockIdx.x * blockDim.x + threadIdx.x) >> 5;
    const int lane = threadIdx.x & 31;
    if (warp >= n_tokens) return;

    // --- dtype detect: 32 aligned u64 words of the prefix (256B, in-bounds
    // for both interpretations; L1-hot broadcast). True int64 ids < 2^32 have
    // zero high words; packed int32 pairs have random nonzero high words.
    const unsigned long long probe =
        ((const unsigned long long*)ids_raw)[lane];
    const bool is64 = !__any_sync(0xFFFFFFFFu, probe > 0xFFFFFFFFull);

    // ids in [0, 1114112): (id+1)*prime fits in int32, result non-negative.
    int id;
    if (is64) id = (int)((const long long*)ids_raw)[warp];
    else      id = ((const int*)ids_raw)[warp];
    const int idp = id + 1;

    // Lane l owns the bucket for hash (l & 7); gathers fetch it via shuffle.
    const int my_prime  = (int)((PACKED_PRIMES >> ((lane & 7) * 8)) & 0xFF);
    const int my_bucket = (idp * my_prime) & (NUM_BUCKETS - 1);

    // Gather 6 float4s per lane. float4 index j = lane + 32*k in [0,192).
    // Hash shard h = j/24 (24 float4s per shard); reference hidden layout
    // puts hash h at columns [96h, 96h+96).
    // float4 index into tables: h*393216 + bucket*24 + (j - 24h)
    //                         = h*393192 + bucket*24 + j.
    const float4* t4 = reinterpret_cast<const float4*>(tables);
    float4 v[6];
#pragma unroll
    for (int k = 0; k < 6; k++) {
        const int j   = lane + 32 * k;
        const int h   = j / 24;
        const int bkt = __shfl_sync(0xFFFFFFFFu, my_bucket, h);
        v[k] = __ldg(t4 + ((size_t)h * 393192 + (size_t)bkt * 24 + j));
    }

    // Warp reduction: sum and sum-of-squares over 768 values.
    float s = 0.f, ss = 0.f;
#pragma unroll
    for (int k = 0; k < 6; k++) {
        s  += v[k].x + v[k].y + v[k].z + v[k].w;
        ss += v[k].x * v[k].x + v[k].y * v[k].y
            + v[k].z * v[k].z + v[k].w * v[k].w;
    }
#pragma unroll
    for (int d = 16; d > 0; d >>= 1) {
        s  += __shfl_xor_sync(0xFFFFFFFFu, s,  d);
        ss += __shfl_xor_sync(0xFFFFFFFFu, ss, d);
    }

    const float inv_n = 1.0f / (float)HIDDEN;
    const float mean  = s * inv_n;
    const float var   = fmaxf(ss * inv_n - mean * mean, 0.0f);
    const float rstd  = rsqrtf(var + LN_EPS);

    // Normalize + affine; streaming stores (evict-first) keep the 50MB table
    // working set resident in L2 while 201MB of output flows through.
    const float4* sc4 = reinterpret_cast<const float4*>(ln_scale);
    const float4* bi4 = reinterpret_cast<const float4*>(ln_bias);
    float4* o4 = reinterpret_cast<float4*>(out + (size_t)warp * HIDDEN);

#pragma unroll
    for (int k = 0; k < 6; k++) {
        const int j = lane + 32 * k;
        const float4 sc = __ldg(sc4 + j);
        const float4 bi = __ldg(bi4 + j);
        float4 r;
        r.x = (v[k].x - mean) * rstd * sc.x + bi.x;
        r.y = (v[k].y - mean) * rstd * sc.y + bi.y;
        r.z = (v[k].z - mean) * rstd * sc.z + bi.z;
        r.w = (v[k].w - mean) * rstd * sc.w + bi.w;
        __stcs(o4 + j, r);
    }
}

extern "C" void kernel_launch(void* const* d_in, const int* in_sizes, int n_in,
                              void* d_out, int out_size)
{
    const void*  ids    = d_in[0];                 // int32 or int64 input_ids
    const float* tables = (const float*)d_in[1];   // [8,16384,96]
    const float* scale  = (const float*)d_in[2];   // [768]
    const float* bias   = (const float*)d_in[3];   // [768]
    float*       out    = (float*)d_out;

    const int n_tokens = in_sizes[0];              // BATCH*SEQ = 65536
    const int warps_per_block = 256 / 32;          // 8 warps/block
    const int blocks = (n_tokens + warps_per_block - 1) / warps_per_block;
    canine_emb_ln_kernel<<<blocks, 256>>>(ids, tables, scale, bias, out, n_tokens);
}